// round 10
// baseline (speedup 1.0000x reference)
#include <cuda_runtime.h>
#include <cuda_bf16.h>
#include <cuda_fp16.h>
#include <cstdint>

#define NB 8
#define HW 4096
#define CI 256
#define CA 128
#define CO 256
#define INVS 0.08838834764831843f
#define PSC  0.015625f
#define PSCI 64.0f

// ---- flash SMEM layout ----
#define QJ_OFF   0
#define QJ_BUF   16384
#define FEAT_OFF 32768
#define FEAT_BUF 32768
#define P_OFF    98304
#define MJ_OFF   106496
#define LRED_OFF 107008
#define SMEM_TOTAL 107520

// ---- proj SMEM layout ----
#define PW_OFF   0
#define PX_OFF   32768
#define QT_OFF   65536
#define PROJ_SMEM 100352

__device__ __half g_q[NB * HW * CA];
__device__ __half g_featT[(size_t)NB * CO * HW];
__device__ __half g_xh[(size_t)NB * CI * HW];
__device__ __half g_wh[(CO + CA) * CI];
__device__ float g_scale[CO + CA];
__device__ float g_bias[CO + CA];

__device__ __forceinline__ uint32_t smem_u32(const void* p) {
    uint32_t a;
    asm("{ .reg .u64 t; cvta.to.shared.u64 t, %1; cvt.u32.u64 %0, t; }" : "=r"(a) : "l"(p));
    return a;
}
#define CP16(dst, src) asm volatile("cp.async.cg.shared.global [%0], [%1], 16;" :: "r"(dst), "l"(src))
#define CP_COMMIT()    asm volatile("cp.async.commit_group;" ::: "memory")
#define CP_WAIT1()     asm volatile("cp.async.wait_group 1;" ::: "memory")
#define CP_WAIT0()     asm volatile("cp.async.wait_group 0;" ::: "memory")

#define LDSM_X4(r0, r1, r2, r3, addr) \
    asm volatile("ldmatrix.sync.aligned.m8n8.x4.shared.b16 {%0,%1,%2,%3}, [%4];" \
        : "=r"(r0), "=r"(r1), "=r"(r2), "=r"(r3) : "r"(addr))
#define LDSM_X4T(r0, r1, r2, r3, addr) \
    asm volatile("ldmatrix.sync.aligned.m8n8.x4.trans.shared.b16 {%0,%1,%2,%3}, [%4];" \
        : "=r"(r0), "=r"(r1), "=r"(r2), "=r"(r3) : "r"(addr))

__device__ __forceinline__ void mma_f16(float* d, const uint32_t* a, const uint32_t* b) {
    asm volatile("mma.sync.aligned.m16n8k16.row.col.f32.f16.f16.f32 "
        "{%0,%1,%2,%3}, {%4,%5,%6,%7}, {%8,%9}, {%0,%1,%2,%3};"
        : "+f"(d[0]), "+f"(d[1]), "+f"(d[2]), "+f"(d[3])
        : "r"(a[0]), "r"(a[1]), "r"(a[2]), "r"(a[3]), "r"(b[0]), "r"(b[1]));
}

__global__ void prep_kernel(const float* __restrict__ rg, const float* __restrict__ rb,
                            const float* __restrict__ rm, const float* __restrict__ rv,
                            const float* __restrict__ ag, const float* __restrict__ ab,
                            const float* __restrict__ am, const float* __restrict__ av) {
    int o = threadIdx.x;
    if (o < CO) {
        float inv = rg[o] * rsqrtf(rv[o] + 1e-5f);
        g_scale[o] = inv; g_bias[o] = rb[o] - rm[o] * inv;
    } else if (o < CO + CA) {
        int a = o - CO;
        float inv = ag[a] * rsqrtf(av[a] + 1e-5f);
        g_scale[o] = inv; g_bias[o] = ab[a] - am[a] * inv;
    }
}

#define XN4 2097152
#define WN4 24576
__global__ __launch_bounds__(256) void convert_kernel(const float4* __restrict__ x,
                                                      const float4* __restrict__ rw,
                                                      const float4* __restrict__ aw) {
    int idx = blockIdx.x * 256 + threadIdx.x;
    if (idx < XN4) {
        float4 v = x[idx];
        __half2 h0 = __floats2half2_rn(v.x, v.y);
        __half2 h1 = __floats2half2_rn(v.z, v.w);
        *(uint2*)(g_xh + (size_t)idx * 4) = make_uint2(*(uint32_t*)&h0, *(uint32_t*)&h1);
    } else {
        int widx = idx - XN4;
        if (widx < WN4) {
            float4 v = (widx < 16384) ? rw[widx] : aw[widx - 16384];
            __half2 h0 = __floats2half2_rn(v.x, v.y);
            __half2 h1 = __floats2half2_rn(v.z, v.w);
            *(uint2*)(g_wh + widx * 4) = make_uint2(*(uint32_t*)&h0, *(uint32_t*)&h1);
        }
    }
}

// HMMA projection (unchanged from R9)
__global__ __launch_bounds__(256) void proj_mma(float* dummy) {
    extern __shared__ __align__(16) char sm[];
    const uint32_t smb = smem_u32(sm);
    const int pb = blockIdx.x * 128, ob = blockIdx.y, n = blockIdx.z;
    const int tid = threadIdx.x, w = tid >> 5, lane = tid & 31;
    const int gid = lane >> 2, tig = lane & 3;
    const int lq = lane >> 3, lr = lane & 7;
    const int wo = w & 3, wp = w >> 2;

    uint32_t arow[2];
#pragma unroll
    for (int mt = 0; mt < 2; mt++)
        arow[mt] = (uint32_t)((wo * 32 + mt * 16 + ((lq & 1) ? 8 : 0) + lr) * 128);
    const int ac0 = (lq & 2) >> 1;
    const uint32_t brow0 = (uint32_t)((((lq & 1) ? 8 : 0) + lr) * 256);
    const int bc0 = wp * 8 + ((lq & 2) >> 1);

    auto loadchunk = [&](int c, int buf) {
        const uint32_t wsb = smb + PW_OFF + buf * 16384;
#pragma unroll
        for (int it = 0; it < 4; it++) {
            int e = tid + it * 256, row = e >> 3, ch = e & 7;
            CP16(wsb + row * 128 + ((ch ^ (row & 7)) << 4),
                 (const char*)(g_wh + (ob * 128 + row) * CI + c * 64 + ch * 8));
        }
        const uint32_t xsb = smb + PX_OFF + buf * 16384;
#pragma unroll
        for (int it = 0; it < 4; it++) {
            int e = tid + it * 256, row = e >> 4, ch = e & 15;
            CP16(xsb + row * 256 + ((ch ^ (row & 7)) << 4),
                 (const char*)(g_xh + ((size_t)(n * CI + c * 64 + row)) * HW + pb + ch * 8));
        }
        CP_COMMIT();
    };

    float acc[2][8][4];
#pragma unroll
    for (int mt = 0; mt < 2; mt++)
#pragma unroll
        for (int nb = 0; nb < 8; nb++)
#pragma unroll
            for (int r = 0; r < 4; r++) acc[mt][nb][r] = 0.f;

    loadchunk(0, 0);
    for (int c = 0; c < 4; c++) {
        __syncthreads();
        if (c < 3) { loadchunk(c + 1, (c + 1) & 1); CP_WAIT1(); } else { CP_WAIT0(); }
        __syncthreads();
        const int buf = c & 1;
        const uint32_t wsb = smb + PW_OFF + buf * 16384;
        const uint32_t xsb = smb + PX_OFF + buf * 16384;
#pragma unroll
        for (int ks = 0; ks < 4; ks++) {
            uint32_t a[2][4];
#pragma unroll
            for (int mt = 0; mt < 2; mt++)
                LDSM_X4(a[mt][0], a[mt][1], a[mt][2], a[mt][3],
                        wsb + arow[mt] + (((ks * 2 + ac0) ^ lr) << 4));
            const uint32_t brb = xsb + brow0 + ks * 16 * 256;
#pragma unroll
            for (int u = 0; u < 4; u++) {
                uint32_t r0, r1, r2, r3;
                LDSM_X4T(r0, r1, r2, r3, brb + (((bc0 + u * 2) ^ lr) << 4));
                uint32_t bL[2] = {r0, r1}, bR[2] = {r2, r3};
                mma_f16(acc[0][u * 2],     a[0], bL);
                mma_f16(acc[0][u * 2 + 1], a[0], bR);
                mma_f16(acc[1][u * 2],     a[1], bL);
                mma_f16(acc[1][u * 2 + 1], a[1], bR);
            }
        }
    }
    __syncthreads();

    if (ob < 2) {
#pragma unroll
        for (int mt = 0; mt < 2; mt++) {
            int o = ob * 128 + wo * 32 + mt * 16 + gid;
            float sc0 = g_scale[o], bs0 = g_bias[o];
            float sc8 = g_scale[o + 8], bs8 = g_bias[o + 8];
#pragma unroll
            for (int nb = 0; nb < 8; nb++) {
                int p = pb + wp * 64 + nb * 8 + 2 * tig;
                float v0 = fmaxf(fmaf(acc[mt][nb][0], sc0, bs0), 0.f);
                float v1 = fmaxf(fmaf(acc[mt][nb][1], sc0, bs0), 0.f);
                float v2 = fmaxf(fmaf(acc[mt][nb][2], sc8, bs8), 0.f);
                float v3 = fmaxf(fmaf(acc[mt][nb][3], sc8, bs8), 0.f);
                __half2 h0 = __floats2half2_rn(v0, v1);
                __half2 h1 = __floats2half2_rn(v2, v3);
                *(uint32_t*)(g_featT + ((size_t)n * CO + o) * HW + p) = *(uint32_t*)&h0;
                *(uint32_t*)(g_featT + ((size_t)n * CO + o + 8) * HW + p) = *(uint32_t*)&h1;
            }
        }
    } else {
        __half* qsm = (__half*)(sm + QT_OFF);
#pragma unroll
        for (int mt = 0; mt < 2; mt++) {
            int ol = wo * 32 + mt * 16 + gid;
            float sc0 = g_scale[CO + ol], bs0 = g_bias[CO + ol];
            float sc8 = g_scale[CO + ol + 8], bs8 = g_bias[CO + ol + 8];
#pragma unroll
            for (int nb = 0; nb < 8; nb++) {
                int pl = wp * 64 + nb * 8 + 2 * tig;
                qsm[pl * 136 + ol]           = __float2half(fmaxf(fmaf(acc[mt][nb][0], sc0, bs0), 0.f));
                qsm[(pl + 1) * 136 + ol]     = __float2half(fmaxf(fmaf(acc[mt][nb][1], sc0, bs0), 0.f));
                qsm[pl * 136 + ol + 8]       = __float2half(fmaxf(fmaf(acc[mt][nb][2], sc8, bs8), 0.f));
                qsm[(pl + 1) * 136 + ol + 8] = __float2half(fmaxf(fmaf(acc[mt][nb][3], sc8, bs8), 0.f));
            }
        }
        __syncthreads();
#pragma unroll
        for (int it = 0; it < 8; it++) {
            int e = tid + it * 256, row = e >> 4, ch = e & 15;
            *(uint4*)(g_q + ((size_t)(n * HW + pb + row)) * CA + ch * 8) =
                *(uint4*)((char*)qsm + row * 272 + ch * 16);
        }
    }
}

// flash attention: PV re-split (c-quarter x i-half per warp)
__global__ __launch_bounds__(256, 2) void flash_kernel(const float* __restrict__ mask,
                                                       float* __restrict__ out) {
    extern __shared__ __align__(16) char sm[];
    const uint32_t smb = smem_u32(sm);
    const int n = blockIdx.y, ib = blockIdx.x * 64;
    const int tid = threadIdx.x, w = tid >> 5, lane = tid & 31;
    const int gid = lane >> 2, tig = lane & 3;
    const int g = w >> 1, jh = w & 1;            // QK roles
    const int cq = w & 3, ih = w >> 2;           // PV roles
    const int lq = lane >> 3, lr = lane & 7;

    uint32_t qjrow[2];
#pragma unroll
    for (int u = 0; u < 2; u++)
        qjrow[u] = (uint32_t)((jh * 32 + u * 16 + ((lq & 2) ? 8 : 0) + lr) * 256);
    const int qk_c0 = lq & 1;
    const uint32_t pvarow = (uint32_t)((cq * 64 + ((lq & 1) ? 8 : 0) + lr) * 128);
    const int pva_c0 = (lq & 2) >> 1;
    const uint32_t pvbrow = smb + P_OFF + (uint32_t)((ih * 32 + ((lq & 2) ? 8 : 0) + lr) * 128);
    const int pvb_c0 = lq & 1;

    uint32_t ah[8][4];
    {
        const size_t r0 = (size_t)(n * HW + ib + g * 16 + gid) * CA;
        const size_t r1 = r0 + 8 * CA;
#pragma unroll
        for (int ks = 0; ks < 8; ks++) {
            int c0 = ks * 16 + 2 * tig;
            ah[ks][0] = *(const uint32_t*)(g_q + r0 + c0);
            ah[ks][1] = *(const uint32_t*)(g_q + r1 + c0);
            ah[ks][2] = *(const uint32_t*)(g_q + r0 + c0 + 8);
            ah[ks][3] = *(const uint32_t*)(g_q + r1 + c0 + 8);
        }
    }

    auto prefetch = [&](int t) {
        const int buf = t & 1, jb = t * 64;
        const uint32_t qh = smb + QJ_OFF + buf * QJ_BUF;
#pragma unroll
        for (int it = 0; it < 4; it++) {
            int e = tid + it * 256, row = e >> 4, ch = e & 15;
            CP16(qh + row * 256 + ((ch ^ (row & 7)) << 4),
                 (const char*)(g_q + (size_t)(n * HW + jb + row) * CA + ch * 8));
        }
        const uint32_t fb = smb + FEAT_OFF + buf * FEAT_BUF;
#pragma unroll
        for (int it = 0; it < 8; it++) {
            int e = tid + it * 256, row = e >> 3, ch = e & 7;
            CP16(fb + row * 128 + ((ch ^ (row & 7)) << 4),
                 (const char*)(g_featT + ((size_t)n * CO + row) * HW + jb + ch * 8));
        }
        if (tid < 16)
            CP16(smb + MJ_OFF + buf * 256 + tid * 16, (const char*)(mask + n * HW + jb + tid * 4));
        CP_COMMIT();
    };

    float dacc[4][4][4];
#pragma unroll
    for (int mt = 0; mt < 4; mt++)
#pragma unroll
        for (int nb = 0; nb < 4; nb++)
#pragma unroll
            for (int r = 0; r < 4; r++) dacc[mt][nb][r] = 0.f;
    float l0 = 0.f, l1 = 0.f;

    prefetch(0);

    for (int t = 0; t < 64; t++) {
        __syncthreads();
        if (t < 63) { prefetch(t + 1); CP_WAIT1(); } else { CP_WAIT0(); }
        __syncthreads();
        const int buf = t & 1;

        // ---- QK: S[16i x 32j] ----
        float s[4][4];
#pragma unroll
        for (int jq = 0; jq < 4; jq++)
#pragma unroll
            for (int r = 0; r < 4; r++) s[jq][r] = 0.f;
        const uint32_t qbase = smb + QJ_OFF + buf * QJ_BUF;
#pragma unroll
        for (int ks = 0; ks < 8; ks++) {
            uint32_t ch = (uint32_t)(((ks * 2 + qk_c0) ^ lr) << 4);
#pragma unroll
            for (int u = 0; u < 2; u++) {
                uint32_t r0, r1, r2, r3;
                LDSM_X4(r0, r1, r2, r3, qbase + qjrow[u] + ch);
                uint32_t b0[2] = {r0, r1}, b1[2] = {r2, r3};
                mma_f16(s[u * 2],     ah[ks], b0);
                mma_f16(s[u * 2 + 1], ah[ks], b1);
            }
        }

        // ---- softmax -> scaled fp16 P (swizzled) ----
        const float* mjb = (const float*)(sm + MJ_OFF + buf * 256);
        char* P = sm + P_OFF;
#pragma unroll
        for (int jq = 0; jq < 4; jq++) {
            int j8 = jh * 32 + jq * 8;
            float m0 = (mjb[j8 + 2 * tig]     - 1.f) * 1e8f;
            float m1 = (mjb[j8 + 2 * tig + 1] - 1.f) * 1e8f;
            float p0 = __expf(fmaf(s[jq][0], INVS, m0));
            float p1 = __expf(fmaf(s[jq][1], INVS, m1));
            float p2 = __expf(fmaf(s[jq][2], INVS, m0));
            float p3 = __expf(fmaf(s[jq][3], INVS, m1));
            l0 += p0 + p1; l1 += p2 + p3;
            __half2 q01 = __floats2half2_rn(p0 * PSC, p1 * PSC);
            __half2 q23 = __floats2half2_rn(p2 * PSC, p3 * PSC);
            int chn = ((jh * 4 + jq) ^ gid) << 4;
            *(uint32_t*)(P + (g * 16 + gid)     * 128 + chn + tig * 4) = *(uint32_t*)&q01;
            *(uint32_t*)(P + (g * 16 + 8 + gid) * 128 + chn + tig * 4) = *(uint32_t*)&q23;
        }
        // writers of P rows [32ih, 32ih+32) == readers == warps 4ih..4ih+3
        asm volatile("bar.sync %0, 128;" :: "r"(1 + ih) : "memory");

        // ---- PV: dacc[c64 x i32] += feat @ P^T ----
        const uint32_t fbb = smb + FEAT_OFF + buf * FEAT_BUF;
#pragma unroll
        for (int ks = 0; ks < 4; ks++) {
            uint32_t chb = (uint32_t)(((ks * 2 + pvb_c0) ^ lr) << 4);
            uint32_t b0, b1, b2, b3, b4, b5, b6, b7;
            LDSM_X4(b0, b1, b2, b3, pvbrow + chb);
            LDSM_X4(b4, b5, b6, b7, pvbrow + 2048 + chb);
            uint32_t bn0[2] = {b0, b1}, bn1[2] = {b2, b3};
            uint32_t bn2[2] = {b4, b5}, bn3[2] = {b6, b7};
            uint32_t fch = (uint32_t)(((ks * 2 + pva_c0) ^ lr) << 4);
#pragma unroll
            for (int mt = 0; mt < 4; mt++) {
                uint32_t a0, a1, a2, a3;
                LDSM_X4(a0, a1, a2, a3, fbb + pvarow + mt * 2048 + fch);
                uint32_t aa[4] = {a0, a1, a2, a3};
                mma_f16(dacc[mt][0], aa, bn0);
                mma_f16(dacc[mt][1], aa, bn1);
                mma_f16(dacc[mt][2], aa, bn2);
                mma_f16(dacc[mt][3], aa, bn3);
            }
        }
    }

    // ---- l reduction ----
    l0 += __shfl_xor_sync(0xFFFFFFFFu, l0, 1);
    l0 += __shfl_xor_sync(0xFFFFFFFFu, l0, 2);
    l1 += __shfl_xor_sync(0xFFFFFFFFu, l1, 1);
    l1 += __shfl_xor_sync(0xFFFFFFFFu, l1, 2);
    float* lred = (float*)(sm + LRED_OFF);
    __syncthreads();
    if (jh == 0 && tig == 0) { lred[g * 16 + gid] = l0; lred[g * 16 + 8 + gid] = l1; }
    __syncthreads();
    if (jh == 1 && tig == 0) { lred[g * 16 + gid] += l0; lred[g * 16 + 8 + gid] += l1; }
    __syncthreads();

    // ---- epilogue ----
#pragma unroll
    for (int nb = 0; nb < 4; nb++) {
        int i0 = ih * 32 + nb * 8 + 2 * tig;
        float r0 = mask[n * HW + ib + i0]     * PSCI / fmaxf(lred[i0],     1e-30f);
        float r1 = mask[n * HW + ib + i0 + 1] * PSCI / fmaxf(lred[i0 + 1], 1e-30f);
#pragma unroll
        for (int mt = 0; mt < 4; mt++) {
            int c = cq * 64 + mt * 16 + gid;
            float2 v0 = make_float2(dacc[mt][nb][0] * r0, dacc[mt][nb][1] * r1);
            float2 v1 = make_float2(dacc[mt][nb][2] * r0, dacc[mt][nb][3] * r1);
            *(float2*)(out + ((size_t)(n * CO + c))     * HW + ib + i0) = v0;
            *(float2*)(out + ((size_t)(n * CO + c + 8)) * HW + ib + i0) = v1;
        }
    }
}

extern "C" void kernel_launch(void* const* d_in, const int* in_sizes, int n_in,
                              void* d_out, int out_size) {
    const float* x    = (const float*)d_in[0];
    const float* mask = (const float*)d_in[1];
    prep_kernel<<<1, CO + CA>>>((const float*)d_in[3], (const float*)d_in[4],
                                (const float*)d_in[5], (const float*)d_in[6],
                                (const float*)d_in[8], (const float*)d_in[9],
                                (const float*)d_in[10], (const float*)d_in[11]);
    convert_kernel<<<(XN4 + WN4) / 256, 256>>>((const float4*)x,
                                               (const float4*)d_in[2],
                                               (const float4*)d_in[7]);
    cudaFuncSetAttribute(proj_mma, cudaFuncAttributeMaxDynamicSharedMemorySize, PROJ_SMEM);
    dim3 gproj(HW / 128, 3, NB);
    proj_mma<<<gproj, 256, PROJ_SMEM>>>(nullptr);

    cudaFuncSetAttribute(flash_kernel, cudaFuncAttributeMaxDynamicSharedMemorySize, SMEM_TOTAL);
    dim3 gfl(HW / 64, NB);
    flash_kernel<<<gfl, 256, SMEM_TOTAL>>>(mask, (float*)d_out);
}

// round 11
// speedup vs baseline: 1.2613x; 1.2613x over previous
#include <cuda_runtime.h>
#include <cuda_bf16.h>
#include <cuda_fp16.h>
#include <cstdint>

#define NB 8
#define HW 4096
#define CI 256
#define CA 128
#define CO 256
#define INVS 0.08838834764831843f
#define C1E  (0.08838834764831843f * 1.4426950408889634f)
#define MBIG 1.44269504e8f

// ---- flash SMEM layout ----
#define QJ_OFF   0
#define QJ_BUF   16384
#define FEAT_OFF 32768
#define FEAT_BUF 32768
#define P_OFF    98304
#define MJ_OFF   106496
#define LRED_OFF 107008
#define SMEM_TOTAL 107520

// ---- proj SMEM layout ----
#define PW_OFF   0
#define PX_OFF   32768
#define QT_OFF   65536
#define PROJ_SMEM 100352

__device__ __half g_q[NB * HW * CA];
__device__ __half g_featT[(size_t)NB * CO * HW];
__device__ __half g_xh[(size_t)NB * CI * HW];
__device__ __half g_wh[(CO + CA) * CI];
__device__ float g_scale[CO + CA];
__device__ float g_bias[CO + CA];

__device__ __forceinline__ uint32_t smem_u32(const void* p) {
    uint32_t a;
    asm("{ .reg .u64 t; cvta.to.shared.u64 t, %1; cvt.u32.u64 %0, t; }" : "=r"(a) : "l"(p));
    return a;
}
#define CP16(dst, src) asm volatile("cp.async.cg.shared.global [%0], [%1], 16;" :: "r"(dst), "l"(src))
#define CP_COMMIT()    asm volatile("cp.async.commit_group;" ::: "memory")
#define CP_WAIT1()     asm volatile("cp.async.wait_group 1;" ::: "memory")
#define CP_WAIT0()     asm volatile("cp.async.wait_group 0;" ::: "memory")

#define LDSM_X4(r0, r1, r2, r3, addr) \
    asm volatile("ldmatrix.sync.aligned.m8n8.x4.shared.b16 {%0,%1,%2,%3}, [%4];" \
        : "=r"(r0), "=r"(r1), "=r"(r2), "=r"(r3) : "r"(addr))
#define LDSM_X4T(r0, r1, r2, r3, addr) \
    asm volatile("ldmatrix.sync.aligned.m8n8.x4.trans.shared.b16 {%0,%1,%2,%3}, [%4];" \
        : "=r"(r0), "=r"(r1), "=r"(r2), "=r"(r3) : "r"(addr))

__device__ __forceinline__ void mma_f16(float* d, const uint32_t* a, const uint32_t* b) {
    asm volatile("mma.sync.aligned.m16n8k16.row.col.f32.f16.f16.f32 "
        "{%0,%1,%2,%3}, {%4,%5,%6,%7}, {%8,%9}, {%0,%1,%2,%3};"
        : "+f"(d[0]), "+f"(d[1]), "+f"(d[2]), "+f"(d[3])
        : "r"(a[0]), "r"(a[1]), "r"(a[2]), "r"(a[3]), "r"(b[0]), "r"(b[1]));
}

__global__ void prep_kernel(const float* __restrict__ rg, const float* __restrict__ rb,
                            const float* __restrict__ rm, const float* __restrict__ rv,
                            const float* __restrict__ ag, const float* __restrict__ ab,
                            const float* __restrict__ am, const float* __restrict__ av) {
    int o = threadIdx.x;
    if (o < CO) {
        float inv = rg[o] * rsqrtf(rv[o] + 1e-5f);
        g_scale[o] = inv; g_bias[o] = rb[o] - rm[o] * inv;
    } else if (o < CO + CA) {
        int a = o - CO;
        float inv = ag[a] * rsqrtf(av[a] + 1e-5f);
        g_scale[o] = inv; g_bias[o] = ab[a] - am[a] * inv;
    }
}

#define XN4 2097152
#define WN4 24576
__global__ __launch_bounds__(256) void convert_kernel(const float4* __restrict__ x,
                                                      const float4* __restrict__ rw,
                                                      const float4* __restrict__ aw) {
    int idx = blockIdx.x * 256 + threadIdx.x;
    if (idx < XN4) {
        float4 v = x[idx];
        __half2 h0 = __floats2half2_rn(v.x, v.y);
        __half2 h1 = __floats2half2_rn(v.z, v.w);
        *(uint2*)(g_xh + (size_t)idx * 4) = make_uint2(*(uint32_t*)&h0, *(uint32_t*)&h1);
    } else {
        int widx = idx - XN4;
        if (widx < WN4) {
            float4 v = (widx < 16384) ? rw[widx] : aw[widx - 16384];
            __half2 h0 = __floats2half2_rn(v.x, v.y);
            __half2 h1 = __floats2half2_rn(v.z, v.w);
            *(uint2*)(g_wh + widx * 4) = make_uint2(*(uint32_t*)&h0, *(uint32_t*)&h1);
        }
    }
}

// HMMA projection (unchanged)
__global__ __launch_bounds__(256) void proj_mma(float* dummy) {
    extern __shared__ __align__(16) char sm[];
    const uint32_t smb = smem_u32(sm);
    const int pb = blockIdx.x * 128, ob = blockIdx.y, n = blockIdx.z;
    const int tid = threadIdx.x, w = tid >> 5, lane = tid & 31;
    const int gid = lane >> 2, tig = lane & 3;
    const int lq = lane >> 3, lr = lane & 7;
    const int wo = w & 3, wp = w >> 2;

    uint32_t arow[2];
#pragma unroll
    for (int mt = 0; mt < 2; mt++)
        arow[mt] = (uint32_t)((wo * 32 + mt * 16 + ((lq & 1) ? 8 : 0) + lr) * 128);
    const int ac0 = (lq & 2) >> 1;
    const uint32_t brow0 = (uint32_t)((((lq & 1) ? 8 : 0) + lr) * 256);
    const int bc0 = wp * 8 + ((lq & 2) >> 1);

    auto loadchunk = [&](int c, int buf) {
        const uint32_t wsb = smb + PW_OFF + buf * 16384;
#pragma unroll
        for (int it = 0; it < 4; it++) {
            int e = tid + it * 256, row = e >> 3, ch = e & 7;
            CP16(wsb + row * 128 + ((ch ^ (row & 7)) << 4),
                 (const char*)(g_wh + (ob * 128 + row) * CI + c * 64 + ch * 8));
        }
        const uint32_t xsb = smb + PX_OFF + buf * 16384;
#pragma unroll
        for (int it = 0; it < 4; it++) {
            int e = tid + it * 256, row = e >> 4, ch = e & 15;
            CP16(xsb + row * 256 + ((ch ^ (row & 7)) << 4),
                 (const char*)(g_xh + ((size_t)(n * CI + c * 64 + row)) * HW + pb + ch * 8));
        }
        CP_COMMIT();
    };

    float acc[2][8][4];
#pragma unroll
    for (int mt = 0; mt < 2; mt++)
#pragma unroll
        for (int nb = 0; nb < 8; nb++)
#pragma unroll
            for (int r = 0; r < 4; r++) acc[mt][nb][r] = 0.f;

    loadchunk(0, 0);
    for (int c = 0; c < 4; c++) {
        __syncthreads();
        if (c < 3) { loadchunk(c + 1, (c + 1) & 1); CP_WAIT1(); } else { CP_WAIT0(); }
        __syncthreads();
        const int buf = c & 1;
        const uint32_t wsb = smb + PW_OFF + buf * 16384;
        const uint32_t xsb = smb + PX_OFF + buf * 16384;
#pragma unroll
        for (int ks = 0; ks < 4; ks++) {
            uint32_t a[2][4];
#pragma unroll
            for (int mt = 0; mt < 2; mt++)
                LDSM_X4(a[mt][0], a[mt][1], a[mt][2], a[mt][3],
                        wsb + arow[mt] + (((ks * 2 + ac0) ^ lr) << 4));
            const uint32_t brb = xsb + brow0 + ks * 16 * 256;
#pragma unroll
            for (int u = 0; u < 4; u++) {
                uint32_t r0, r1, r2, r3;
                LDSM_X4T(r0, r1, r2, r3, brb + (((bc0 + u * 2) ^ lr) << 4));
                uint32_t bL[2] = {r0, r1}, bR[2] = {r2, r3};
                mma_f16(acc[0][u * 2],     a[0], bL);
                mma_f16(acc[0][u * 2 + 1], a[0], bR);
                mma_f16(acc[1][u * 2],     a[1], bL);
                mma_f16(acc[1][u * 2 + 1], a[1], bR);
            }
        }
    }
    __syncthreads();

    if (ob < 2) {
#pragma unroll
        for (int mt = 0; mt < 2; mt++) {
            int o = ob * 128 + wo * 32 + mt * 16 + gid;
            float sc0 = g_scale[o], bs0 = g_bias[o];
            float sc8 = g_scale[o + 8], bs8 = g_bias[o + 8];
#pragma unroll
            for (int nb = 0; nb < 8; nb++) {
                int p = pb + wp * 64 + nb * 8 + 2 * tig;
                float v0 = fmaxf(fmaf(acc[mt][nb][0], sc0, bs0), 0.f);
                float v1 = fmaxf(fmaf(acc[mt][nb][1], sc0, bs0), 0.f);
                float v2 = fmaxf(fmaf(acc[mt][nb][2], sc8, bs8), 0.f);
                float v3 = fmaxf(fmaf(acc[mt][nb][3], sc8, bs8), 0.f);
                __half2 h0 = __floats2half2_rn(v0, v1);
                __half2 h1 = __floats2half2_rn(v2, v3);
                *(uint32_t*)(g_featT + ((size_t)n * CO + o) * HW + p) = *(uint32_t*)&h0;
                *(uint32_t*)(g_featT + ((size_t)n * CO + o + 8) * HW + p) = *(uint32_t*)&h1;
            }
        }
    } else {
        __half* qsm = (__half*)(sm + QT_OFF);
#pragma unroll
        for (int mt = 0; mt < 2; mt++) {
            int ol = wo * 32 + mt * 16 + gid;
            float sc0 = g_scale[CO + ol], bs0 = g_bias[CO + ol];
            float sc8 = g_scale[CO + ol + 8], bs8 = g_bias[CO + ol + 8];
#pragma unroll
            for (int nb = 0; nb < 8; nb++) {
                int pl = wp * 64 + nb * 8 + 2 * tig;
                qsm[pl * 136 + ol]           = __float2half(fmaxf(fmaf(acc[mt][nb][0], sc0, bs0), 0.f));
                qsm[(pl + 1) * 136 + ol]     = __float2half(fmaxf(fmaf(acc[mt][nb][1], sc0, bs0), 0.f));
                qsm[pl * 136 + ol + 8]       = __float2half(fmaxf(fmaf(acc[mt][nb][2], sc8, bs8), 0.f));
                qsm[(pl + 1) * 136 + ol + 8] = __float2half(fmaxf(fmaf(acc[mt][nb][3], sc8, bs8), 0.f));
            }
        }
        __syncthreads();
#pragma unroll
        for (int it = 0; it < 8; it++) {
            int e = tid + it * 256, row = e >> 4, ch = e & 15;
            *(uint4*)(g_q + ((size_t)(n * HW + pb + row)) * CA + ch * 8) =
                *(uint4*)((char*)qsm + row * 272 + ch * 16);
        }
    }
}

// flash attention: R9 layout + ex2.approx.f16x2 softmax
__global__ __launch_bounds__(256, 2) void flash_kernel(const float* __restrict__ mask,
                                                       float* __restrict__ out) {
    extern __shared__ __align__(16) char sm[];
    const uint32_t smb = smem_u32(sm);
    const int n = blockIdx.y, ib = blockIdx.x * 64;
    const int tid = threadIdx.x, w = tid >> 5, lane = tid & 31;
    const int gid = lane >> 2, tig = lane & 3;
    const int g = w >> 1, jh = w & 1;
    const int lq = lane >> 3, lr = lane & 7;

    uint32_t qjrow[2];
#pragma unroll
    for (int u = 0; u < 2; u++)
        qjrow[u] = (uint32_t)((jh * 32 + u * 16 + ((lq & 2) ? 8 : 0) + lr) * 256);
    const int qk_c0 = lq & 1;
    const uint32_t pvarow = (uint32_t)((jh * 128 + ((lq & 1) ? 8 : 0) + lr) * 128);
    const int pva_c0 = (lq & 2) >> 1;
    const uint32_t pvbrow = smb + P_OFF + (uint32_t)((g * 16 + ((lq & 2) ? 8 : 0) + lr) * 128);
    const int pvb_c0 = lq & 1;

    uint32_t ah[8][4];
    {
        const size_t r0 = (size_t)(n * HW + ib + g * 16 + gid) * CA;
        const size_t r1 = r0 + 8 * CA;
#pragma unroll
        for (int ks = 0; ks < 8; ks++) {
            int c0 = ks * 16 + 2 * tig;
            ah[ks][0] = *(const uint32_t*)(g_q + r0 + c0);
            ah[ks][1] = *(const uint32_t*)(g_q + r1 + c0);
            ah[ks][2] = *(const uint32_t*)(g_q + r0 + c0 + 8);
            ah[ks][3] = *(const uint32_t*)(g_q + r1 + c0 + 8);
        }
    }

    auto prefetch = [&](int t) {
        const int buf = t & 1, jb = t * 64;
        const uint32_t qh = smb + QJ_OFF + buf * QJ_BUF;
#pragma unroll
        for (int it = 0; it < 4; it++) {
            int e = tid + it * 256, row = e >> 4, ch = e & 15;
            CP16(qh + row * 256 + ((ch ^ (row & 7)) << 4),
                 (const char*)(g_q + (size_t)(n * HW + jb + row) * CA + ch * 8));
        }
        const uint32_t fb = smb + FEAT_OFF + buf * FEAT_BUF;
#pragma unroll
        for (int it = 0; it < 8; it++) {
            int e = tid + it * 256, row = e >> 3, ch = e & 7;
            CP16(fb + row * 128 + ((ch ^ (row & 7)) << 4),
                 (const char*)(g_featT + ((size_t)n * CO + row) * HW + jb + ch * 8));
        }
        if (tid < 16)
            CP16(smb + MJ_OFF + buf * 256 + tid * 16, (const char*)(mask + n * HW + jb + tid * 4));
        CP_COMMIT();
    };

    float dacc[8][2][4];
#pragma unroll
    for (int mt = 0; mt < 8; mt++)
#pragma unroll
        for (int nb = 0; nb < 2; nb++)
#pragma unroll
            for (int r = 0; r < 4; r++) dacc[mt][nb][r] = 0.f;
    float l0 = 0.f, l1 = 0.f;

    prefetch(0);

    for (int t = 0; t < 64; t++) {
        __syncthreads();
        if (t < 63) { prefetch(t + 1); CP_WAIT1(); } else { CP_WAIT0(); }
        __syncthreads();
        const int buf = t & 1;

        // ---- QK: S[16i x 32j] ----
        float s[4][4];
#pragma unroll
        for (int jq = 0; jq < 4; jq++)
#pragma unroll
            for (int r = 0; r < 4; r++) s[jq][r] = 0.f;
        const uint32_t qbase = smb + QJ_OFF + buf * QJ_BUF;
#pragma unroll
        for (int ks = 0; ks < 8; ks++) {
            uint32_t ch = (uint32_t)(((ks * 2 + qk_c0) ^ lr) << 4);
#pragma unroll
            for (int u = 0; u < 2; u++) {
                uint32_t r0, r1, r2, r3;
                LDSM_X4(r0, r1, r2, r3, qbase + qjrow[u] + ch);
                uint32_t b0[2] = {r0, r1}, b1[2] = {r2, r3};
                mma_f16(s[u * 2],     ah[ks], b0);
                mma_f16(s[u * 2 + 1], ah[ks], b1);
            }
        }

        // ---- softmax via ex2.approx.f16x2: e = s*INVS*log2e + mterm - 6 ----
        const float* mjb = (const float*)(sm + MJ_OFF + buf * 256);
        char* P = sm + P_OFF;
        uint32_t lac0 = 0, lac1 = 0;   // half2 accumulators
#pragma unroll
        for (int jq = 0; jq < 4; jq++) {
            int j8 = jh * 32 + jq * 8;
            // mterm: 0 for mask=1, -1.44e8 for mask=0 (exact via FMA), then -6 shift
            float m0e = fmaf(mjb[j8 + 2 * tig],     MBIG, -MBIG) - 6.f;
            float m1e = fmaf(mjb[j8 + 2 * tig + 1], MBIG, -MBIG) - 6.f;
            float e0 = fmaf(s[jq][0], C1E, m0e);
            float e1 = fmaf(s[jq][1], C1E, m1e);
            float e2 = fmaf(s[jq][2], C1E, m0e);
            float e3 = fmaf(s[jq][3], C1E, m1e);
            uint32_t h01, h23, p01, p23;
            asm("cvt.rn.f16x2.f32 %0, %1, %2;" : "=r"(h01) : "f"(e1), "f"(e0));
            asm("cvt.rn.f16x2.f32 %0, %1, %2;" : "=r"(h23) : "f"(e3), "f"(e2));
            asm("ex2.approx.f16x2 %0, %1;" : "=r"(p01) : "r"(h01));
            asm("ex2.approx.f16x2 %0, %1;" : "=r"(p23) : "r"(h23));
            int chn = ((jh * 4 + jq) ^ gid) << 4;
            *(uint32_t*)(P + (g * 16 + gid)     * 128 + chn + tig * 4) = p01;
            *(uint32_t*)(P + (g * 16 + 8 + gid) * 128 + chn + tig * 4) = p23;
            asm("add.f16x2 %0, %0, %1;" : "+r"(lac0) : "r"(p01));
            asm("add.f16x2 %0, %0, %1;" : "+r"(lac1) : "r"(p23));
        }
        {
            float2 f0 = __half22float2(*(__half2*)&lac0);
            float2 f1 = __half22float2(*(__half2*)&lac1);
            l0 += f0.x + f0.y;
            l1 += f1.x + f1.y;
        }
        asm volatile("bar.sync %0, 64;" :: "r"(1 + g) : "memory");

        // ---- PV: dacc[c16 x i16] += feat @ P^T ----
        const uint32_t fbb = smb + FEAT_OFF + buf * FEAT_BUF;
#pragma unroll
        for (int ks = 0; ks < 4; ks++) {
            uint32_t bp0, bp1, bp2, bp3;
            LDSM_X4(bp0, bp1, bp2, bp3, pvbrow + (((ks * 2 + pvb_c0) ^ lr) << 4));
            uint32_t bL[2] = {bp0, bp1}, bR[2] = {bp2, bp3};
            uint32_t fch = (uint32_t)(((ks * 2 + pva_c0) ^ lr) << 4);
#pragma unroll
            for (int mt = 0; mt < 8; mt++) {
                uint32_t a0, a1, a2, a3;
                LDSM_X4(a0, a1, a2, a3, fbb + pvarow + mt * (16 * 128) + fch);
                uint32_t aa[4] = {a0, a1, a2, a3};
                mma_f16(dacc[mt][0], aa, bL);
                mma_f16(dacc[mt][1], aa, bR);
            }
        }
    }

    // ---- l reduction ----
    l0 += __shfl_xor_sync(0xFFFFFFFFu, l0, 1);
    l0 += __shfl_xor_sync(0xFFFFFFFFu, l0, 2);
    l1 += __shfl_xor_sync(0xFFFFFFFFu, l1, 1);
    l1 += __shfl_xor_sync(0xFFFFFFFFu, l1, 2);
    float* lred = (float*)(sm + LRED_OFF);
    __syncthreads();
    if (jh == 0 && tig == 0) { lred[g * 16 + gid] = l0; lred[g * 16 + 8 + gid] = l1; }
    __syncthreads();
    if (jh == 1 && tig == 0) { lred[g * 16 + gid] += l0; lred[g * 16 + 8 + gid] += l1; }
    __syncthreads();

    // ---- epilogue: out = dacc / l * mask (l and P consistently scaled) ----
#pragma unroll
    for (int nb = 0; nb < 2; nb++) {
        int i0 = g * 16 + nb * 8 + 2 * tig;
        float r0 = mask[n * HW + ib + i0]     / fmaxf(lred[i0],     1e-30f);
        float r1 = mask[n * HW + ib + i0 + 1] / fmaxf(lred[i0 + 1], 1e-30f);
#pragma unroll
        for (int mt = 0; mt < 8; mt++) {
            int c = jh * 128 + mt * 16 + gid;
            float2 v0 = make_float2(dacc[mt][nb][0] * r0, dacc[mt][nb][1] * r1);
            float2 v1 = make_float2(dacc[mt][nb][2] * r0, dacc[mt][nb][3] * r1);
            *(float2*)(out + ((size_t)(n * CO + c))     * HW + ib + i0) = v0;
            *(float2*)(out + ((size_t)(n * CO + c + 8)) * HW + ib + i0) = v1;
        }
    }
}

extern "C" void kernel_launch(void* const* d_in, const int* in_sizes, int n_in,
                              void* d_out, int out_size) {
    const float* x    = (const float*)d_in[0];
    const float* mask = (const float*)d_in[1];
    prep_kernel<<<1, CO + CA>>>((const float*)d_in[3], (const float*)d_in[4],
                                (const float*)d_in[5], (const float*)d_in[6],
                                (const float*)d_in[8], (const float*)d_in[9],
                                (const float*)d_in[10], (const float*)d_in[11]);
    convert_kernel<<<(XN4 + WN4) / 256, 256>>>((const float4*)x,
                                               (const float4*)d_in[2],
                                               (const float4*)d_in[7]);
    cudaFuncSetAttribute(proj_mma, cudaFuncAttributeMaxDynamicSharedMemorySize, PROJ_SMEM);
    dim3 gproj(HW / 128, 3, NB);
    proj_mma<<<gproj, 256, PROJ_SMEM>>>(nullptr);

    cudaFuncSetAttribute(flash_kernel, cudaFuncAttributeMaxDynamicSharedMemorySize, SMEM_TOTAL);
    dim3 gfl(HW / 64, NB);
    flash_kernel<<<gfl, 256, SMEM_TOTAL>>>(mask, (float*)d_out);
}

// round 12
// speedup vs baseline: 1.2936x; 1.0256x over previous
#include <cuda_runtime.h>
#include <cuda_bf16.h>
#include <cuda_fp16.h>
#include <cstdint>

#define NB 8
#define HW 4096
#define CI 256
#define CA 128
#define CO 256
#define INVS 0.08838834764831843f
#define C1E  (0.08838834764831843f * 1.4426950408889634f)
#define MBIG 1.44269504e8f

// ---- flash SMEM layout ----
#define QJ_OFF   0
#define QJ_BUF   16384
#define FEAT_OFF 32768
#define FEAT_BUF 32768
#define P_OFF    98304
#define MJ_OFF   106496      // 3 x 256
#define LRED_OFF 107264      // 256
#define SMEM_TOTAL 107520

// ---- proj SMEM layout ----
#define PW_OFF   0
#define PX_OFF   32768
#define QT_OFF   65536
#define PROJ_SMEM 100352

__device__ __half g_q[NB * HW * CA];
__device__ __half g_featT[(size_t)NB * CO * HW];
__device__ __half g_xh[(size_t)NB * CI * HW];
__device__ __half g_wh[(CO + CA) * CI];
__device__ float g_scale[CO + CA];
__device__ float g_bias[CO + CA];

__device__ __forceinline__ uint32_t smem_u32(const void* p) {
    uint32_t a;
    asm("{ .reg .u64 t; cvta.to.shared.u64 t, %1; cvt.u32.u64 %0, t; }" : "=r"(a) : "l"(p));
    return a;
}
#define CP16(dst, src) asm volatile("cp.async.cg.shared.global [%0], [%1], 16;" :: "r"(dst), "l"(src))
#define CP_COMMIT()    asm volatile("cp.async.commit_group;" ::: "memory")
#define CP_WAIT1()     asm volatile("cp.async.wait_group 1;" ::: "memory")
#define CP_WAIT0()     asm volatile("cp.async.wait_group 0;" ::: "memory")

#define LDSM_X4(r0, r1, r2, r3, addr) \
    asm volatile("ldmatrix.sync.aligned.m8n8.x4.shared.b16 {%0,%1,%2,%3}, [%4];" \
        : "=r"(r0), "=r"(r1), "=r"(r2), "=r"(r3) : "r"(addr))
#define LDSM_X4T(r0, r1, r2, r3, addr) \
    asm volatile("ldmatrix.sync.aligned.m8n8.x4.trans.shared.b16 {%0,%1,%2,%3}, [%4];" \
        : "=r"(r0), "=r"(r1), "=r"(r2), "=r"(r3) : "r"(addr))

__device__ __forceinline__ void mma_f16(float* d, const uint32_t* a, const uint32_t* b) {
    asm volatile("mma.sync.aligned.m16n8k16.row.col.f32.f16.f16.f32 "
        "{%0,%1,%2,%3}, {%4,%5,%6,%7}, {%8,%9}, {%0,%1,%2,%3};"
        : "+f"(d[0]), "+f"(d[1]), "+f"(d[2]), "+f"(d[3])
        : "r"(a[0]), "r"(a[1]), "r"(a[2]), "r"(a[3]), "r"(b[0]), "r"(b[1]));
}

__global__ void prep_kernel(const float* __restrict__ rg, const float* __restrict__ rb,
                            const float* __restrict__ rm, const float* __restrict__ rv,
                            const float* __restrict__ ag, const float* __restrict__ ab,
                            const float* __restrict__ am, const float* __restrict__ av) {
    int o = threadIdx.x;
    if (o < CO) {
        float inv = rg[o] * rsqrtf(rv[o] + 1e-5f);
        g_scale[o] = inv; g_bias[o] = rb[o] - rm[o] * inv;
    } else if (o < CO + CA) {
        int a = o - CO;
        float inv = ag[a] * rsqrtf(av[a] + 1e-5f);
        g_scale[o] = inv; g_bias[o] = ab[a] - am[a] * inv;
    }
}

#define XN4 2097152
#define WN4 24576
__global__ __launch_bounds__(256) void convert_kernel(const float4* __restrict__ x,
                                                      const float4* __restrict__ rw,
                                                      const float4* __restrict__ aw) {
    int idx = blockIdx.x * 256 + threadIdx.x;
    if (idx < XN4) {
        float4 v = x[idx];
        __half2 h0 = __floats2half2_rn(v.x, v.y);
        __half2 h1 = __floats2half2_rn(v.z, v.w);
        *(uint2*)(g_xh + (size_t)idx * 4) = make_uint2(*(uint32_t*)&h0, *(uint32_t*)&h1);
    } else {
        int widx = idx - XN4;
        if (widx < WN4) {
            float4 v = (widx < 16384) ? rw[widx] : aw[widx - 16384];
            __half2 h0 = __floats2half2_rn(v.x, v.y);
            __half2 h1 = __floats2half2_rn(v.z, v.w);
            *(uint2*)(g_wh + widx * 4) = make_uint2(*(uint32_t*)&h0, *(uint32_t*)&h1);
        }
    }
}

// HMMA projection (unchanged)
__global__ __launch_bounds__(256) void proj_mma(float* dummy) {
    extern __shared__ __align__(16) char sm[];
    const uint32_t smb = smem_u32(sm);
    const int pb = blockIdx.x * 128, ob = blockIdx.y, n = blockIdx.z;
    const int tid = threadIdx.x, w = tid >> 5, lane = tid & 31;
    const int gid = lane >> 2, tig = lane & 3;
    const int lq = lane >> 3, lr = lane & 7;
    const int wo = w & 3, wp = w >> 2;

    uint32_t arow[2];
#pragma unroll
    for (int mt = 0; mt < 2; mt++)
        arow[mt] = (uint32_t)((wo * 32 + mt * 16 + ((lq & 1) ? 8 : 0) + lr) * 128);
    const int ac0 = (lq & 2) >> 1;
    const uint32_t brow0 = (uint32_t)((((lq & 1) ? 8 : 0) + lr) * 256);
    const int bc0 = wp * 8 + ((lq & 2) >> 1);

    auto loadchunk = [&](int c, int buf) {
        const uint32_t wsb = smb + PW_OFF + buf * 16384;
#pragma unroll
        for (int it = 0; it < 4; it++) {
            int e = tid + it * 256, row = e >> 3, ch = e & 7;
            CP16(wsb + row * 128 + ((ch ^ (row & 7)) << 4),
                 (const char*)(g_wh + (ob * 128 + row) * CI + c * 64 + ch * 8));
        }
        const uint32_t xsb = smb + PX_OFF + buf * 16384;
#pragma unroll
        for (int it = 0; it < 4; it++) {
            int e = tid + it * 256, row = e >> 4, ch = e & 15;
            CP16(xsb + row * 256 + ((ch ^ (row & 7)) << 4),
                 (const char*)(g_xh + ((size_t)(n * CI + c * 64 + row)) * HW + pb + ch * 8));
        }
        CP_COMMIT();
    };

    float acc[2][8][4];
#pragma unroll
    for (int mt = 0; mt < 2; mt++)
#pragma unroll
        for (int nb = 0; nb < 8; nb++)
#pragma unroll
            for (int r = 0; r < 4; r++) acc[mt][nb][r] = 0.f;

    loadchunk(0, 0);
    for (int c = 0; c < 4; c++) {
        __syncthreads();
        if (c < 3) { loadchunk(c + 1, (c + 1) & 1); CP_WAIT1(); } else { CP_WAIT0(); }
        __syncthreads();
        const int buf = c & 1;
        const uint32_t wsb = smb + PW_OFF + buf * 16384;
        const uint32_t xsb = smb + PX_OFF + buf * 16384;
#pragma unroll
        for (int ks = 0; ks < 4; ks++) {
            uint32_t a[2][4];
#pragma unroll
            for (int mt = 0; mt < 2; mt++)
                LDSM_X4(a[mt][0], a[mt][1], a[mt][2], a[mt][3],
                        wsb + arow[mt] + (((ks * 2 + ac0) ^ lr) << 4));
            const uint32_t brb = xsb + brow0 + ks * 16 * 256;
#pragma unroll
            for (int u = 0; u < 4; u++) {
                uint32_t r0, r1, r2, r3;
                LDSM_X4T(r0, r1, r2, r3, brb + (((bc0 + u * 2) ^ lr) << 4));
                uint32_t bL[2] = {r0, r1}, bR[2] = {r2, r3};
                mma_f16(acc[0][u * 2],     a[0], bL);
                mma_f16(acc[0][u * 2 + 1], a[0], bR);
                mma_f16(acc[1][u * 2],     a[1], bL);
                mma_f16(acc[1][u * 2 + 1], a[1], bR);
            }
        }
    }
    __syncthreads();

    if (ob < 2) {
#pragma unroll
        for (int mt = 0; mt < 2; mt++) {
            int o = ob * 128 + wo * 32 + mt * 16 + gid;
            float sc0 = g_scale[o], bs0 = g_bias[o];
            float sc8 = g_scale[o + 8], bs8 = g_bias[o + 8];
#pragma unroll
            for (int nb = 0; nb < 8; nb++) {
                int p = pb + wp * 64 + nb * 8 + 2 * tig;
                float v0 = fmaxf(fmaf(acc[mt][nb][0], sc0, bs0), 0.f);
                float v1 = fmaxf(fmaf(acc[mt][nb][1], sc0, bs0), 0.f);
                float v2 = fmaxf(fmaf(acc[mt][nb][2], sc8, bs8), 0.f);
                float v3 = fmaxf(fmaf(acc[mt][nb][3], sc8, bs8), 0.f);
                __half2 h0 = __floats2half2_rn(v0, v1);
                __half2 h1 = __floats2half2_rn(v2, v3);
                *(uint32_t*)(g_featT + ((size_t)n * CO + o) * HW + p) = *(uint32_t*)&h0;
                *(uint32_t*)(g_featT + ((size_t)n * CO + o + 8) * HW + p) = *(uint32_t*)&h1;
            }
        }
    } else {
        __half* qsm = (__half*)(sm + QT_OFF);
#pragma unroll
        for (int mt = 0; mt < 2; mt++) {
            int ol = wo * 32 + mt * 16 + gid;
            float sc0 = g_scale[CO + ol], bs0 = g_bias[CO + ol];
            float sc8 = g_scale[CO + ol + 8], bs8 = g_bias[CO + ol + 8];
#pragma unroll
            for (int nb = 0; nb < 8; nb++) {
                int pl = wp * 64 + nb * 8 + 2 * tig;
                qsm[pl * 136 + ol]           = __float2half(fmaxf(fmaf(acc[mt][nb][0], sc0, bs0), 0.f));
                qsm[(pl + 1) * 136 + ol]     = __float2half(fmaxf(fmaf(acc[mt][nb][1], sc0, bs0), 0.f));
                qsm[pl * 136 + ol + 8]       = __float2half(fmaxf(fmaf(acc[mt][nb][2], sc8, bs8), 0.f));
                qsm[(pl + 1) * 136 + ol + 8] = __float2half(fmaxf(fmaf(acc[mt][nb][3], sc8, bs8), 0.f));
            }
        }
        __syncthreads();
#pragma unroll
        for (int it = 0; it < 8; it++) {
            int e = tid + it * 256, row = e >> 4, ch = e & 15;
            *(uint4*)(g_q + ((size_t)(n * HW + pb + row)) * CA + ch * 8) =
                *(uint4*)((char*)qsm + row * 272 + ch * 16);
        }
    }
}

// flash attention: cross-iteration software pipeline (s carried), f16x2 softmax
__global__ __launch_bounds__(256, 2) void flash_kernel(const float* __restrict__ mask,
                                                       float* __restrict__ out) {
    extern __shared__ __align__(16) char sm[];
    const uint32_t smb = smem_u32(sm);
    const int n = blockIdx.y, ib = blockIdx.x * 64;
    const int tid = threadIdx.x, w = tid >> 5, lane = tid & 31;
    const int gid = lane >> 2, tig = lane & 3;
    const int g = w >> 1, jh = w & 1;
    const int lq = lane >> 3, lr = lane & 7;

    uint32_t qjrow[2];
#pragma unroll
    for (int u = 0; u < 2; u++)
        qjrow[u] = (uint32_t)((jh * 32 + u * 16 + ((lq & 2) ? 8 : 0) + lr) * 256);
    const int qk_c0 = lq & 1;
    const uint32_t pvarow = (uint32_t)((jh * 128 + ((lq & 1) ? 8 : 0) + lr) * 128);
    const int pva_c0 = (lq & 2) >> 1;
    const uint32_t pvbrow = smb + P_OFF + (uint32_t)((g * 16 + ((lq & 2) ? 8 : 0) + lr) * 128);
    const int pvb_c0 = lq & 1;

    uint32_t ah[8][4];
    {
        const size_t r0 = (size_t)(n * HW + ib + g * 16 + gid) * CA;
        const size_t r1 = r0 + 8 * CA;
#pragma unroll
        for (int ks = 0; ks < 8; ks++) {
            int c0 = ks * 16 + 2 * tig;
            ah[ks][0] = *(const uint32_t*)(g_q + r0 + c0);
            ah[ks][1] = *(const uint32_t*)(g_q + r1 + c0);
            ah[ks][2] = *(const uint32_t*)(g_q + r0 + c0 + 8);
            ah[ks][3] = *(const uint32_t*)(g_q + r1 + c0 + 8);
        }
    }

    // ---- split loaders (explicit buffer/slot targets) ----
    auto load_qj = [&](int t) {        // -> qj buf t&1
        const uint32_t qh = smb + QJ_OFF + (t & 1) * QJ_BUF;
        const int jb = t * 64;
#pragma unroll
        for (int it = 0; it < 4; it++) {
            int e = tid + it * 256, row = e >> 4, ch = e & 15;
            CP16(qh + row * 256 + ((ch ^ (row & 7)) << 4),
                 (const char*)(g_q + (size_t)(n * HW + jb + row) * CA + ch * 8));
        }
    };
    auto load_feat = [&](int t) {      // -> feat buf t&1
        const uint32_t fb = smb + FEAT_OFF + (t & 1) * FEAT_BUF;
        const int jb = t * 64;
#pragma unroll
        for (int it = 0; it < 8; it++) {
            int e = tid + it * 256, row = e >> 3, ch = e & 7;
            CP16(fb + row * 128 + ((ch ^ (row & 7)) << 4),
                 (const char*)(g_featT + ((size_t)n * CO + row) * HW + jb + ch * 8));
        }
    };
    auto load_mj = [&](int t) {        // -> mj slot t%3
        if (tid < 16)
            CP16(smb + MJ_OFF + (t % 3) * 256 + tid * 16,
                 (const char*)(mask + n * HW + t * 64 + tid * 4));
    };

    float s[4][4];
    auto do_qk = [&](int t) {          // qj buf t&1 -> s
#pragma unroll
        for (int jq = 0; jq < 4; jq++)
#pragma unroll
            for (int r = 0; r < 4; r++) s[jq][r] = 0.f;
        const uint32_t qbase = smb + QJ_OFF + (t & 1) * QJ_BUF;
#pragma unroll
        for (int ks = 0; ks < 8; ks++) {
            uint32_t ch = (uint32_t)(((ks * 2 + qk_c0) ^ lr) << 4);
#pragma unroll
            for (int u = 0; u < 2; u++) {
                uint32_t r0, r1, r2, r3;
                LDSM_X4(r0, r1, r2, r3, qbase + qjrow[u] + ch);
                uint32_t b0[2] = {r0, r1}, b1[2] = {r2, r3};
                mma_f16(s[u * 2],     ah[ks], b0);
                mma_f16(s[u * 2 + 1], ah[ks], b1);
            }
        }
    };

    float dacc[8][2][4];
#pragma unroll
    for (int mt = 0; mt < 8; mt++)
#pragma unroll
        for (int nb = 0; nb < 2; nb++)
#pragma unroll
            for (int r = 0; r < 4; r++) dacc[mt][nb][r] = 0.f;
    float l0 = 0.f, l1 = 0.f;

    // ---- prologue: G_A={qj0,mj0}, G_B={qj1,feat0,mj1}; then QK(0) ----
    load_qj(0); load_mj(0); CP_COMMIT();
    load_qj(1); load_feat(0); load_mj(1); CP_COMMIT();
    CP_WAIT1();                       // G_A done
    __syncthreads();
    do_qk(0);

    for (int t = 0; t < 64; t++) {
        __syncthreads();              // (A) all warps done with iter t-1 reads
        // G_t: qj(t+2)->buf t&1, feat(t+1)->buf (t+1)&1, mj(t+2)
        if (t + 2 < 64) { load_qj(t + 2); load_mj(t + 2); }
        if (t + 1 < 64) load_feat(t + 1);
        CP_COMMIT();
        CP_WAIT1();                   // G_{t-1} done: qj(t+1), feat(t), mj(t)... ready
        __syncthreads();              // (B) cross-warp visibility

        // ---- softmax(t): s (computed last iter) -> P ----
        const float* mjb = (const float*)(sm + MJ_OFF + (t % 3) * 256);
        char* P = sm + P_OFF;
        uint32_t lac0 = 0, lac1 = 0;
#pragma unroll
        for (int jq = 0; jq < 4; jq++) {
            int j8 = jh * 32 + jq * 8;
            float m0e = fmaf(mjb[j8 + 2 * tig],     MBIG, -MBIG) - 6.f;
            float m1e = fmaf(mjb[j8 + 2 * tig + 1], MBIG, -MBIG) - 6.f;
            float e0 = fmaf(s[jq][0], C1E, m0e);
            float e1 = fmaf(s[jq][1], C1E, m1e);
            float e2 = fmaf(s[jq][2], C1E, m0e);
            float e3 = fmaf(s[jq][3], C1E, m1e);
            uint32_t h01, h23, p01, p23;
            asm("cvt.rn.f16x2.f32 %0, %1, %2;" : "=r"(h01) : "f"(e1), "f"(e0));
            asm("cvt.rn.f16x2.f32 %0, %1, %2;" : "=r"(h23) : "f"(e3), "f"(e2));
            asm("ex2.approx.f16x2 %0, %1;" : "=r"(p01) : "r"(h01));
            asm("ex2.approx.f16x2 %0, %1;" : "=r"(p23) : "r"(h23));
            int chn = ((jh * 4 + jq) ^ gid) << 4;
            *(uint32_t*)(P + (g * 16 + gid)     * 128 + chn + tig * 4) = p01;
            *(uint32_t*)(P + (g * 16 + 8 + gid) * 128 + chn + tig * 4) = p23;
            asm("add.f16x2 %0, %0, %1;" : "+r"(lac0) : "r"(p01));
            asm("add.f16x2 %0, %0, %1;" : "+r"(lac1) : "r"(p23));
        }
        {
            float2 f0 = __half22float2(*(__half2*)&lac0);
            float2 f1 = __half22float2(*(__half2*)&lac1);
            l0 += f0.x + f0.y;
            l1 += f1.x + f1.y;
        }
        asm volatile("bar.sync %0, 64;" :: "r"(1 + g) : "memory");

        // ---- QK(t+1): refill s (consumed above) ----
        if (t + 1 < 64) do_qk(t + 1);

        // ---- PV(t): dacc += feat(t) @ P^T ----
        const uint32_t fbb = smb + FEAT_OFF + (t & 1) * FEAT_BUF;
#pragma unroll
        for (int ks = 0; ks < 4; ks++) {
            uint32_t bp0, bp1, bp2, bp3;
            LDSM_X4(bp0, bp1, bp2, bp3, pvbrow + (((ks * 2 + pvb_c0) ^ lr) << 4));
            uint32_t bL[2] = {bp0, bp1}, bR[2] = {bp2, bp3};
            uint32_t fch = (uint32_t)(((ks * 2 + pva_c0) ^ lr) << 4);
#pragma unroll
            for (int mt = 0; mt < 8; mt++) {
                uint32_t a0, a1, a2, a3;
                LDSM_X4(a0, a1, a2, a3, fbb + pvarow + mt * (16 * 128) + fch);
                uint32_t aa[4] = {a0, a1, a2, a3};
                mma_f16(dacc[mt][0], aa, bL);
                mma_f16(dacc[mt][1], aa, bR);
            }
        }
    }

    // ---- l reduction ----
    l0 += __shfl_xor_sync(0xFFFFFFFFu, l0, 1);
    l0 += __shfl_xor_sync(0xFFFFFFFFu, l0, 2);
    l1 += __shfl_xor_sync(0xFFFFFFFFu, l1, 1);
    l1 += __shfl_xor_sync(0xFFFFFFFFu, l1, 2);
    float* lred = (float*)(sm + LRED_OFF);
    __syncthreads();
    if (jh == 0 && tig == 0) { lred[g * 16 + gid] = l0; lred[g * 16 + 8 + gid] = l1; }
    __syncthreads();
    if (jh == 1 && tig == 0) { lred[g * 16 + gid] += l0; lred[g * 16 + 8 + gid] += l1; }
    __syncthreads();

    // ---- epilogue ----
#pragma unroll
    for (int nb = 0; nb < 2; nb++) {
        int i0 = g * 16 + nb * 8 + 2 * tig;
        float r0 = mask[n * HW + ib + i0]     / fmaxf(lred[i0],     1e-30f);
        float r1 = mask[n * HW + ib + i0 + 1] / fmaxf(lred[i0 + 1], 1e-30f);
#pragma unroll
        for (int mt = 0; mt < 8; mt++) {
            int c = jh * 128 + mt * 16 + gid;
            float2 v0 = make_float2(dacc[mt][nb][0] * r0, dacc[mt][nb][1] * r1);
            float2 v1 = make_float2(dacc[mt][nb][2] * r0, dacc[mt][nb][3] * r1);
            *(float2*)(out + ((size_t)(n * CO + c))     * HW + ib + i0) = v0;
            *(float2*)(out + ((size_t)(n * CO + c + 8)) * HW + ib + i0) = v1;
        }
    }
}

extern "C" void kernel_launch(void* const* d_in, const int* in_sizes, int n_in,
                              void* d_out, int out_size) {
    const float* x    = (const float*)d_in[0];
    const float* mask = (const float*)d_in[1];
    prep_kernel<<<1, CO + CA>>>((const float*)d_in[3], (const float*)d_in[4],
                                (const float*)d_in[5], (const float*)d_in[6],
                                (const float*)d_in[8], (const float*)d_in[9],
                                (const float*)d_in[10], (const float*)d_in[11]);
    convert_kernel<<<(XN4 + WN4) / 256, 256>>>((const float4*)x,
                                               (const float4*)d_in[2],
                                               (const float4*)d_in[7]);
    cudaFuncSetAttribute(proj_mma, cudaFuncAttributeMaxDynamicSharedMemorySize, PROJ_SMEM);
    dim3 gproj(HW / 128, 3, NB);
    proj_mma<<<gproj, 256, PROJ_SMEM>>>(nullptr);

    cudaFuncSetAttribute(flash_kernel, cudaFuncAttributeMaxDynamicSharedMemorySize, SMEM_TOTAL);
    dim3 gfl(HW / 64, NB);
    flash_kernel<<<gfl, 256, SMEM_TOTAL>>>(mask, (float*)d_out);
}